// round 11
// baseline (speedup 1.0000x reference)
#include <cuda_runtime.h>
#include <cuda_fp16.h>
#include <cstdint>

#define NN 12288
#define EE 196608
#define DD 64
#define KSPLIT 3
#define CHPS 64                   // chunks of BK=64 per split (192 total / 3)
#define NSTG 4
#define ROW_H 72                  // fp16 row pitch: 64 halves + 8 pad = 144 B
#define A_STAGE_B (128 * ROW_H * 2)     // 18432
#define B_STAGE_B (64 * ROW_H * 2)      // 9216
#define STAGE_B (A_STAGE_B + B_STAGE_B) // 27648
#define SM_GEMM (NSTG * STAGE_B)        // 110592 (x2 CTAs = 221184 <= 228KB/SM)
#define XW_ROW_F 68
#define XW_T_PITCH 136
#define SM_XW (2 * 128 * XW_ROW_F * 4)  // 69632

// scratch (device globals — no allocation allowed)
__device__ __half g_Rth[DD * NN]; // relu(x @ Wh^T)^T as fp16, [feat][node]
__device__ __half g_XWh[NN * DD]; // x @ Wc^T as fp16, [node][64]
__device__ int    g_deg[NN];

// ---------------------------------------------------------------------------
__device__ __forceinline__ uint32_t smem_u32(const void* p) {
    uint32_t a;
    asm("{ .reg .u64 t; cvta.to.shared.u64 t, %1; cvt.u32.u64 %0, t; }"
        : "=r"(a) : "l"(p));
    return a;
}

__device__ __forceinline__ uint32_t f2tf32(float x) {
    uint32_t t;
    asm("cvt.rna.tf32.f32 %0, %1;" : "=r"(t) : "f"(x));
    return t;
}

__device__ __forceinline__ uint32_t pkh2(float lo, float hi) {
    __half2 h = __floats2half2_rn(lo, hi);
    return *(uint32_t*)&h;
}

__device__ __forceinline__ void cp16(uint32_t dst, const void* src) {
    asm volatile("cp.async.cg.shared.global [%0], [%1], 16;"
                 :: "r"(dst), "l"(__cvta_generic_to_global(src)) : "memory");
}
#define CP_COMMIT() asm volatile("cp.async.commit_group;" ::: "memory")
#define CP_WAIT2()  asm volatile("cp.async.wait_group 2;"  ::: "memory")
#define CP_WAIT0()  asm volatile("cp.async.wait_group 0;"  ::: "memory")

__device__ __forceinline__ void mma_tf32(float* c, const uint32_t* a, const uint32_t* b) {
    asm volatile(
        "mma.sync.aligned.m16n8k8.row.col.f32.tf32.tf32.f32 "
        "{%0,%1,%2,%3}, {%4,%5,%6,%7}, {%8,%9}, {%0,%1,%2,%3};"
        : "+f"(c[0]), "+f"(c[1]), "+f"(c[2]), "+f"(c[3])
        : "r"(a[0]), "r"(a[1]), "r"(a[2]), "r"(a[3]), "r"(b[0]), "r"(b[1]));
}

__device__ __forceinline__ void mma_f16(float* c, const uint32_t* a, const uint32_t* b) {
    asm volatile(
        "mma.sync.aligned.m16n8k16.row.col.f32.f16.f16.f32 "
        "{%0,%1,%2,%3}, {%4,%5,%6,%7}, {%8,%9}, {%0,%1,%2,%3};"
        : "+f"(c[0]), "+f"(c[1]), "+f"(c[2]), "+f"(c[3])
        : "r"(a[0]), "r"(a[1]), "r"(a[2]), "r"(a[3]), "r"(b[0]), "r"(b[1]));
}

__device__ __forceinline__ void red2(float* p, float x, float y) {
    asm volatile("red.global.add.v2.f32 [%0], {%1,%2};"
                 :: "l"(__cvta_generic_to_global(p)), "f"(x), "f"(y) : "memory");
}
__device__ __forceinline__ void red4(float* p, float x, float y, float z, float w) {
    asm volatile("red.global.add.v4.f32 [%0], {%1,%2,%3,%4};"
                 :: "l"(__cvta_generic_to_global(p)), "f"(x), "f"(y), "f"(z), "f"(w)
                 : "memory");
}

// ---------------------------------------------------------------------------
__global__ void k_init(float* __restrict__ out) {
    int i = blockIdx.x * 256 + threadIdx.x;   // grid = NN*DD/256
    out[i] = 0.0f;
    if (i < NN) g_deg[i] = 1;
}

__global__ void k_deg(const int* __restrict__ ei) {
    int e = blockIdx.x * 256 + threadIdx.x;
    if (e < EE) atomicAdd(&g_deg[ei[EE + e]], 1);
}

// ---------------------------------------------------------------------------
// Fused projections via tensor cores: [R | XW] = x @ [Wh ; Wc]^T
// R written as fp16 TRANSPOSED [64][NN] (SMEM bounce), XW as fp16 [NN][64].
// ---------------------------------------------------------------------------
__global__ void __launch_bounds__(256) k_xw(const float* __restrict__ x,
                                            const float* __restrict__ Wh,
                                            const float* __restrict__ Wc) {
    extern __shared__ char smem[];
    const uint32_t sb = smem_u32(smem);
    const float* sX = (const float*)smem;
    const float* sW = (const float*)(smem + 128 * XW_ROW_F * 4);
    const uint32_t sWb = sb + 128 * XW_ROW_F * 4;

    const int tid  = threadIdx.x;
    const int lane = tid & 31;
    const int w    = tid >> 5;
    const int wm   = w >> 1;
    const int wn   = w & 1;
    const int g    = lane >> 2;
    const int t    = lane & 3;
    const int m0   = blockIdx.x * 128;

#pragma unroll
    for (int i = 0; i < 8; ++i) {
        int idx = tid + i * 256;
        int r = idx >> 4, c = idx & 15;
        cp16(sb + r * (XW_ROW_F * 4) + c * 16, x + (size_t)(m0 + r) * 64 + c * 4);
        const float* wsrc = (r < 64) ? (Wh + (size_t)r * 64 + c * 4)
                                     : (Wc + (size_t)(r - 64) * 64 + c * 4);
        cp16(sWb + r * (XW_ROW_F * 4) + c * 16, wsrc);
    }
    CP_COMMIT();
    CP_WAIT0();
    __syncthreads();

    float acc[2][8][4];
#pragma unroll
    for (int mi = 0; mi < 2; ++mi)
#pragma unroll
        for (int ni = 0; ni < 8; ++ni)
#pragma unroll
            for (int q = 0; q < 4; ++q) acc[mi][ni][q] = 0.f;

#pragma unroll
    for (int ks = 0; ks < 8; ++ks) {
        int kc = ks * 8 + t;
        uint32_t a[2][4], b[8][2];
#pragma unroll
        for (int mi = 0; mi < 2; ++mi) {
            int r = wm * 32 + mi * 16 + g;
            a[mi][0] = f2tf32(sX[r * XW_ROW_F + kc]);
            a[mi][1] = f2tf32(sX[(r + 8) * XW_ROW_F + kc]);
            a[mi][2] = f2tf32(sX[r * XW_ROW_F + kc + 4]);
            a[mi][3] = f2tf32(sX[(r + 8) * XW_ROW_F + kc + 4]);
        }
#pragma unroll
        for (int ni = 0; ni < 8; ++ni) {
            int n = wn * 64 + ni * 8 + g;
            b[ni][0] = f2tf32(sW[n * XW_ROW_F + kc]);
            b[ni][1] = f2tf32(sW[n * XW_ROW_F + kc + 4]);
        }
#pragma unroll
        for (int mi = 0; mi < 2; ++mi)
#pragma unroll
            for (int ni = 0; ni < 8; ++ni)
                mma_tf32(acc[mi][ni], a[mi], b[ni]);
    }

    __syncthreads();   // reuse smem as fp16 transpose tile
    __half* sT = (__half*)smem;   // [64 cols][XW_T_PITCH] fp16

#pragma unroll
    for (int mi = 0; mi < 2; ++mi) {
#pragma unroll
        for (int half = 0; half < 2; ++half) {
            int rloc = wm * 32 + mi * 16 + half * 8 + g;   // 0..127
            size_t rb = (size_t)(m0 + rloc) * 64;
#pragma unroll
            for (int ni = 0; ni < 8; ++ni) {
                int c = ni * 8 + t * 2;
                float v0 = acc[mi][ni][half * 2 + 0];
                float v1 = acc[mi][ni][half * 2 + 1];
                if (wn == 0) {
                    sT[(c + 0) * XW_T_PITCH + rloc] = __float2half_rn(fmaxf(v0, 0.f));
                    sT[(c + 1) * XW_T_PITCH + rloc] = __float2half_rn(fmaxf(v1, 0.f));
                } else {
                    *(uint32_t*)&g_XWh[rb + c] = pkh2(v0, v1);
                }
            }
        }
    }
    __syncthreads();

#pragma unroll
    for (int i = 0; i < 4; ++i) {
        int idx = tid + i * 256;        // 0..1023 16B slots
        int c = idx >> 4, j = idx & 15;
        uint4 v = *(const uint4*)&sT[c * XW_T_PITCH + j * 8];
        *(uint4*)&g_Rth[(size_t)c * NN + m0 + j * 8] = v;
    }
}

// ---------------------------------------------------------------------------
// edge scatter straight into out: out[col] += aL * dinv[r]*dinv[c] * XW[row]
// XW gathered as fp16 (halves the random-gather L2 traffic)
// ---------------------------------------------------------------------------
__global__ void __launch_bounds__(256) k_scatter(const int* __restrict__ ei,
                                                 const float* __restrict__ paL,
                                                 float* __restrict__ out) {
    int tt = blockIdx.x * 256 + threadIdx.x;   // grid = EE*16/256
    int e = tt >> 4;
    int q = tt & 15;
    int r = ei[e];
    int c = ei[EE + e];
    float norm = (*paL) * rsqrtf((float)g_deg[r]) * rsqrtf((float)g_deg[c]);
    uint2 hv = *(const uint2*)&g_XWh[(size_t)r * 64 + q * 4];
    float2 f0 = __half22float2(*(__half2*)&hv.x);
    float2 f1 = __half22float2(*(__half2*)&hv.y);
    red4(&out[c * 64 + q * 4], norm * f0.x, norm * f0.y, norm * f1.x, norm * f1.y);
}

// ---------------------------------------------------------------------------
// Main GEMM, fp16 m16n8k16 mma.sync, split-K=3, BK=64, 4-stage pipeline.
// A: LDG fp32 -> cvt fp16 -> STS; B: cp.async fp16 issued 3 chunks ahead.
// 2 CTAs/SM (221KB smem/SM), 288 CTAs.
// Sync protocol per chunk: wait_group 2 -> __syncthreads (publishes B(ct)
// and proves stage (ct-1)%4 free) -> issue copies for ct+3 -> compute ct.
// out += aH*(Lsym@R)_partial  (+ split 0: aL*(selfloop + bias))
// ---------------------------------------------------------------------------
__global__ void __launch_bounds__(256, 2) k_gemm(const float* __restrict__ L,
                                                 const float* __restrict__ bconv,
                                                 const float* __restrict__ paL,
                                                 const float* __restrict__ paH,
                                                 float* __restrict__ out) {
    extern __shared__ char smem[];
    const int tid  = threadIdx.x;
    const int lane = tid & 31;
    const int w    = tid >> 5;
    const int wm   = w >> 1;
    const int wn   = w & 1;
    const int g    = lane >> 2;
    const int t    = lane & 3;
    const int m0   = blockIdx.x * 128;
    const int cb   = blockIdx.y * CHPS;
    const uint32_t sb = smem_u32(smem);

    float acc[2][4][4];
#pragma unroll
    for (int mi = 0; mi < 2; ++mi)
#pragma unroll
        for (int ni = 0; ni < 4; ++ni)
#pragma unroll
            for (int q = 0; q < 4; ++q) acc[mi][ni][q] = 0.f;

    const int arow = tid >> 4;       // base row (8 rows x16 apart)
    const int ac4  = tid & 15;       // float4 col within 64

    float4 rA[8];                    // staged A chunk (fp32 from DRAM)

    auto LDGA = [&](int ct) {
        const float* Ap = L + (size_t)m0 * NN + (size_t)(cb + ct) * 64;
#pragma unroll
        for (int i = 0; i < 8; ++i)
            rA[i] = *(const float4*)(Ap + (size_t)(arow + i * 16) * NN + ac4 * 4);
    };
    auto STSA = [&](int ct) {
        char* aP = smem + (ct % NSTG) * STAGE_B;
#pragma unroll
        for (int i = 0; i < 8; ++i) {
            uint2 h;
            h.x = pkh2(rA[i].x, rA[i].y);
            h.y = pkh2(rA[i].z, rA[i].w);
            *(uint2*)(aP + (arow + i * 16) * (ROW_H * 2) + ac4 * 8) = h;
        }
    };
    auto CPB = [&](int ct) {
        uint32_t bB = sb + (ct % NSTG) * STAGE_B + A_STAGE_B;
        const __half* Bp = g_Rth + (size_t)(cb + ct) * 64;
#pragma unroll
        for (int i = 0; i < 2; ++i) {
            int idx = tid + i * 256;        // 0..511: 64 rows x 8 chunks
            int n = idx >> 3, c = idx & 7;
            cp16(bB + n * (ROW_H * 2) + c * 16, Bp + (size_t)n * NN + c * 8);
        }
    };

    // preamble: stages 0,1,2 filled; A regs staged for chunk 3
    LDGA(0); STSA(0); CPB(0); CP_COMMIT();
    LDGA(1); STSA(1); CPB(1); CP_COMMIT();
    LDGA(2); STSA(2); CPB(2); CP_COMMIT();
    LDGA(3);

    for (int ct = 0; ct < CHPS; ++ct) {
        CP_WAIT2();          // this thread's B(ct) group complete
        __syncthreads();     // publish ALL threads' cp.async B(ct) + STS A(ct);
                             // stage (ct-1)%4 == (ct+3)%4 now provably free

        if (ct + 3 < CHPS) {
            STSA(ct + 3);    // rA holds LDGA(ct+3) from previous iteration
            CPB(ct + 3);
            if (ct + 4 < CHPS) LDGA(ct + 4);
        }
        CP_COMMIT();         // unconditional: keeps group numbering aligned

        const __half* sA = (const __half*)(smem + (ct % NSTG) * STAGE_B);
        const __half* sB = (const __half*)(smem + (ct % NSTG) * STAGE_B + A_STAGE_B);

#pragma unroll
        for (int ks = 0; ks < 4; ++ks) {
            uint32_t a[2][4], b[4][2];
            int kb = ks * 16;
#pragma unroll
            for (int mi = 0; mi < 2; ++mi) {
                int r = wm * 32 + mi * 16 + g;
                a[mi][0] = *(const uint32_t*)&sA[r * ROW_H + kb + 2 * t];
                a[mi][1] = *(const uint32_t*)&sA[(r + 8) * ROW_H + kb + 2 * t];
                a[mi][2] = *(const uint32_t*)&sA[r * ROW_H + kb + 8 + 2 * t];
                a[mi][3] = *(const uint32_t*)&sA[(r + 8) * ROW_H + kb + 8 + 2 * t];
            }
#pragma unroll
            for (int ni = 0; ni < 4; ++ni) {
                int n = wn * 32 + ni * 8 + g;
                b[ni][0] = *(const uint32_t*)&sB[n * ROW_H + kb + 2 * t];
                b[ni][1] = *(const uint32_t*)&sB[n * ROW_H + kb + 8 + 2 * t];
            }
#pragma unroll
            for (int mi = 0; mi < 2; ++mi)
#pragma unroll
                for (int ni = 0; ni < 4; ++ni)
                    mma_f16(acc[mi][ni], a[mi], b[ni]);
        }
    }

    // epilogue: red.v2 accumulate; split 0 adds self-loop + bias
    const float aLv = *paL, aHv = *paH;
    const bool  z0  = (blockIdx.y == 0);
#pragma unroll
    for (int mi = 0; mi < 2; ++mi) {
#pragma unroll
        for (int half = 0; half < 2; ++half) {
            int row = m0 + wm * 32 + mi * 16 + half * 8 + g;
            float d2 = 1.0f / (float)g_deg[row];
            size_t rb = (size_t)row * 64;
#pragma unroll
            for (int ni = 0; ni < 4; ++ni) {
                int c = wn * 32 + ni * 8 + t * 2;
                float vx = aHv * acc[mi][ni][half * 2 + 0];
                float vy = aHv * acc[mi][ni][half * 2 + 1];
                if (z0) {
                    uint32_t hw = *(const uint32_t*)&g_XWh[rb + c];
                    float2 xw = __half22float2(*(__half2*)&hw);
                    float2 bb = *(const float2*)&bconv[c];
                    vx += aLv * (d2 * xw.x + bb.x);
                    vy += aLv * (d2 * xw.y + bb.y);
                }
                red2(&out[rb + c], vx, vy);
            }
        }
    }
}

// ---------------------------------------------------------------------------
extern "C" void kernel_launch(void* const* d_in, const int* in_sizes, int n_in,
                              void* d_out, int out_size) {
    const float* x  = (const float*)d_in[0];
    const int*   ei = (const int*)d_in[1];
    const float* Ls = (const float*)d_in[2];
    const float* Wh = (const float*)d_in[3];
    const float* Wc = (const float*)d_in[4];
    const float* bc = (const float*)d_in[5];
    const float* aL = (const float*)d_in[6];
    const float* aH = (const float*)d_in[7];
    float* out = (float*)d_out;

    cudaFuncSetAttribute(k_xw,   cudaFuncAttributeMaxDynamicSharedMemorySize, SM_XW);
    cudaFuncSetAttribute(k_gemm, cudaFuncAttributeMaxDynamicSharedMemorySize, SM_GEMM);

    // order kept so ncu (-s 5 -c 1) captures k_gemm (4th launch)
    k_init<<<(NN * DD) / 256, 256>>>(out);
    k_deg<<<(EE + 255) / 256, 256>>>(ei);
    k_xw<<<96, 256, SM_XW>>>(x, Wh, Wc);
    k_gemm<<<dim3(96, KSPLIT), 256, SM_GEMM>>>(Ls, bc, aL, aH, out);
    k_scatter<<<(EE * 16) / 256, 256>>>(ei, aL, out);
}

// round 12
// speedup vs baseline: 1.3028x; 1.3028x over previous
#include <cuda_runtime.h>
#include <cuda_fp16.h>
#include <cstdint>

#define NN 12288
#define EE 196608
#define DD 64
#define KSPLIT 3
#define CHPS 64                   // chunks of BK=64 per split (192 total / 3)
#define NSTG 3
#define ROW_H 72                  // fp16 row pitch: 64 halves + 8 pad = 144 B
#define A_STAGE_B (128 * ROW_H * 2)     // 18432
#define B_STAGE_B (64 * ROW_H * 2)      // 9216
#define STAGE_B (A_STAGE_B + B_STAGE_B) // 27648
#define SM_GEMM (NSTG * STAGE_B)        // 82944 (x2 CTAs = 166KB/SM)
#define XW_ROW_F 68
#define XW_T_PITCH 136
#define SM_XW (2 * 128 * XW_ROW_F * 4)  // 69632

// scratch (device globals — no allocation allowed)
__device__ __half g_Rth[DD * NN]; // relu(x @ Wh^T)^T as fp16, [feat][node]
__device__ __half g_XWh[NN * DD]; // x @ Wc^T as fp16, [node][64]
__device__ int    g_deg[NN];

// ---------------------------------------------------------------------------
__device__ __forceinline__ uint32_t smem_u32(const void* p) {
    uint32_t a;
    asm("{ .reg .u64 t; cvta.to.shared.u64 t, %1; cvt.u32.u64 %0, t; }"
        : "=r"(a) : "l"(p));
    return a;
}

__device__ __forceinline__ uint32_t f2tf32(float x) {
    uint32_t t;
    asm("cvt.rna.tf32.f32 %0, %1;" : "=r"(t) : "f"(x));
    return t;
}

__device__ __forceinline__ uint32_t pkh2(float lo, float hi) {
    __half2 h = __floats2half2_rn(lo, hi);
    return *(uint32_t*)&h;
}

__device__ __forceinline__ void cp16(uint32_t dst, const void* src) {
    asm volatile("cp.async.cg.shared.global [%0], [%1], 16;"
                 :: "r"(dst), "l"(__cvta_generic_to_global(src)) : "memory");
}
#define CP_COMMIT() asm volatile("cp.async.commit_group;" ::: "memory")
#define CP_WAIT1()  asm volatile("cp.async.wait_group 1;"  ::: "memory")
#define CP_WAIT0()  asm volatile("cp.async.wait_group 0;"  ::: "memory")

__device__ __forceinline__ void mma_tf32(float* c, const uint32_t* a, const uint32_t* b) {
    asm volatile(
        "mma.sync.aligned.m16n8k8.row.col.f32.tf32.tf32.f32 "
        "{%0,%1,%2,%3}, {%4,%5,%6,%7}, {%8,%9}, {%0,%1,%2,%3};"
        : "+f"(c[0]), "+f"(c[1]), "+f"(c[2]), "+f"(c[3])
        : "r"(a[0]), "r"(a[1]), "r"(a[2]), "r"(a[3]), "r"(b[0]), "r"(b[1]));
}

__device__ __forceinline__ void mma_f16(float* c, const uint32_t* a, const uint32_t* b) {
    asm volatile(
        "mma.sync.aligned.m16n8k16.row.col.f32.f16.f16.f32 "
        "{%0,%1,%2,%3}, {%4,%5,%6,%7}, {%8,%9}, {%0,%1,%2,%3};"
        : "+f"(c[0]), "+f"(c[1]), "+f"(c[2]), "+f"(c[3])
        : "r"(a[0]), "r"(a[1]), "r"(a[2]), "r"(a[3]), "r"(b[0]), "r"(b[1]));
}

__device__ __forceinline__ void red2(float* p, float x, float y) {
    asm volatile("red.global.add.v2.f32 [%0], {%1,%2};"
                 :: "l"(__cvta_generic_to_global(p)), "f"(x), "f"(y) : "memory");
}
__device__ __forceinline__ void red4(float* p, float x, float y, float z, float w) {
    asm volatile("red.global.add.v4.f32 [%0], {%1,%2,%3,%4};"
                 :: "l"(__cvta_generic_to_global(p)), "f"(x), "f"(y), "f"(z), "f"(w)
                 : "memory");
}

// ---------------------------------------------------------------------------
__global__ void k_init(float* __restrict__ out) {
    int i = blockIdx.x * 256 + threadIdx.x;   // grid = NN*DD/256
    out[i] = 0.0f;
    if (i < NN) g_deg[i] = 1;
}

__global__ void k_deg(const int* __restrict__ ei) {
    int e = blockIdx.x * 256 + threadIdx.x;
    if (e < EE) atomicAdd(&g_deg[ei[EE + e]], 1);
}

// ---------------------------------------------------------------------------
// Fused projections via tensor cores: [R | XW] = x @ [Wh ; Wc]^T
// R written as fp16 TRANSPOSED [64][NN] (SMEM bounce), XW as fp16 [NN][64].
// ---------------------------------------------------------------------------
__global__ void __launch_bounds__(256) k_xw(const float* __restrict__ x,
                                            const float* __restrict__ Wh,
                                            const float* __restrict__ Wc) {
    extern __shared__ char smem[];
    const uint32_t sb = smem_u32(smem);
    const float* sX = (const float*)smem;
    const float* sW = (const float*)(smem + 128 * XW_ROW_F * 4);
    const uint32_t sWb = sb + 128 * XW_ROW_F * 4;

    const int tid  = threadIdx.x;
    const int lane = tid & 31;
    const int w    = tid >> 5;
    const int wm   = w >> 1;
    const int wn   = w & 1;
    const int g    = lane >> 2;
    const int t    = lane & 3;
    const int m0   = blockIdx.x * 128;

#pragma unroll
    for (int i = 0; i < 8; ++i) {
        int idx = tid + i * 256;
        int r = idx >> 4, c = idx & 15;
        cp16(sb + r * (XW_ROW_F * 4) + c * 16, x + (size_t)(m0 + r) * 64 + c * 4);
        const float* wsrc = (r < 64) ? (Wh + (size_t)r * 64 + c * 4)
                                     : (Wc + (size_t)(r - 64) * 64 + c * 4);
        cp16(sWb + r * (XW_ROW_F * 4) + c * 16, wsrc);
    }
    CP_COMMIT();
    CP_WAIT0();
    __syncthreads();

    float acc[2][8][4];
#pragma unroll
    for (int mi = 0; mi < 2; ++mi)
#pragma unroll
        for (int ni = 0; ni < 8; ++ni)
#pragma unroll
            for (int q = 0; q < 4; ++q) acc[mi][ni][q] = 0.f;

#pragma unroll
    for (int ks = 0; ks < 8; ++ks) {
        int kc = ks * 8 + t;
        uint32_t a[2][4], b[8][2];
#pragma unroll
        for (int mi = 0; mi < 2; ++mi) {
            int r = wm * 32 + mi * 16 + g;
            a[mi][0] = f2tf32(sX[r * XW_ROW_F + kc]);
            a[mi][1] = f2tf32(sX[(r + 8) * XW_ROW_F + kc]);
            a[mi][2] = f2tf32(sX[r * XW_ROW_F + kc + 4]);
            a[mi][3] = f2tf32(sX[(r + 8) * XW_ROW_F + kc + 4]);
        }
#pragma unroll
        for (int ni = 0; ni < 8; ++ni) {
            int n = wn * 64 + ni * 8 + g;
            b[ni][0] = f2tf32(sW[n * XW_ROW_F + kc]);
            b[ni][1] = f2tf32(sW[n * XW_ROW_F + kc + 4]);
        }
#pragma unroll
        for (int mi = 0; mi < 2; ++mi)
#pragma unroll
            for (int ni = 0; ni < 8; ++ni)
                mma_tf32(acc[mi][ni], a[mi], b[ni]);
    }

    __syncthreads();   // reuse smem as fp16 transpose tile
    __half* sT = (__half*)smem;   // [64 cols][XW_T_PITCH] fp16

#pragma unroll
    for (int mi = 0; mi < 2; ++mi) {
#pragma unroll
        for (int half = 0; half < 2; ++half) {
            int rloc = wm * 32 + mi * 16 + half * 8 + g;   // 0..127
            size_t rb = (size_t)(m0 + rloc) * 64;
#pragma unroll
            for (int ni = 0; ni < 8; ++ni) {
                int c = ni * 8 + t * 2;
                float v0 = acc[mi][ni][half * 2 + 0];
                float v1 = acc[mi][ni][half * 2 + 1];
                if (wn == 0) {
                    sT[(c + 0) * XW_T_PITCH + rloc] = __float2half_rn(fmaxf(v0, 0.f));
                    sT[(c + 1) * XW_T_PITCH + rloc] = __float2half_rn(fmaxf(v1, 0.f));
                } else {
                    *(uint32_t*)&g_XWh[rb + c] = pkh2(v0, v1);
                }
            }
        }
    }
    __syncthreads();

#pragma unroll
    for (int i = 0; i < 4; ++i) {
        int idx = tid + i * 256;        // 0..1023 16B slots
        int c = idx >> 4, j = idx & 15;
        uint4 v = *(const uint4*)&sT[c * XW_T_PITCH + j * 8];
        *(uint4*)&g_Rth[(size_t)c * NN + m0 + j * 8] = v;
    }
}

// ---------------------------------------------------------------------------
// edge scatter straight into out: out[col] += aL * dinv[r]*dinv[c] * XW[row]
// XW gathered as fp16 (halves the random-gather L2 traffic)
// ---------------------------------------------------------------------------
__global__ void __launch_bounds__(256) k_scatter(const int* __restrict__ ei,
                                                 const float* __restrict__ paL,
                                                 float* __restrict__ out) {
    int tt = blockIdx.x * 256 + threadIdx.x;   // grid = EE*16/256
    int e = tt >> 4;
    int q = tt & 15;
    int r = ei[e];
    int c = ei[EE + e];
    float norm = (*paL) * rsqrtf((float)g_deg[r]) * rsqrtf((float)g_deg[c]);
    uint2 hv = *(const uint2*)&g_XWh[(size_t)r * 64 + q * 4];
    float2 f0 = __half22float2(*(__half2*)&hv.x);
    float2 f1 = __half22float2(*(__half2*)&hv.y);
    red4(&out[c * 64 + q * 4], norm * f0.x, norm * f0.y, norm * f1.x, norm * f1.y);
}

// ---------------------------------------------------------------------------
// Main GEMM, fp16 m16n8k16 mma.sync, split-K=3, BK=64, 3-stage pipeline
// (R10-proven config). A: LDG fp32 -> cvt fp16 -> STS; B: cp.async fp16.
// 2 CTAs/SM (166KB smem/SM), 288 CTAs.
// Sync protocol per chunk: wait_group 1 -> __syncthreads (publishes B(ct)
// and proves stage (ct-1)%3 free) -> issue copies for ct+2 -> compute ct.
// out += aH*(Lsym@R)_partial  (+ split 0: aL*(selfloop + bias))
// ---------------------------------------------------------------------------
__global__ void __launch_bounds__(256, 2) k_gemm(const float* __restrict__ L,
                                                 const float* __restrict__ bconv,
                                                 const float* __restrict__ paL,
                                                 const float* __restrict__ paH,
                                                 float* __restrict__ out) {
    extern __shared__ char smem[];
    const int tid  = threadIdx.x;
    const int lane = tid & 31;
    const int w    = tid >> 5;
    const int wm   = w >> 1;
    const int wn   = w & 1;
    const int g    = lane >> 2;
    const int t    = lane & 3;
    const int m0   = blockIdx.x * 128;
    const int cb   = blockIdx.y * CHPS;
    const uint32_t sb = smem_u32(smem);

    float acc[2][4][4];
#pragma unroll
    for (int mi = 0; mi < 2; ++mi)
#pragma unroll
        for (int ni = 0; ni < 4; ++ni)
#pragma unroll
            for (int q = 0; q < 4; ++q) acc[mi][ni][q] = 0.f;

    const int arow = tid >> 4;       // base row (8 rows x16 apart)
    const int ac4  = tid & 15;       // float4 col within 64

    float4 rA[8];                    // staged A chunk (fp32 from DRAM)

    auto LDGA = [&](int ct) {
        const float* Ap = L + (size_t)m0 * NN + (size_t)(cb + ct) * 64;
#pragma unroll
        for (int i = 0; i < 8; ++i)
            rA[i] = *(const float4*)(Ap + (size_t)(arow + i * 16) * NN + ac4 * 4);
    };
    auto STSA = [&](int ct) {
        char* aP = smem + (ct % NSTG) * STAGE_B;
#pragma unroll
        for (int i = 0; i < 8; ++i) {
            uint2 h;
            h.x = pkh2(rA[i].x, rA[i].y);
            h.y = pkh2(rA[i].z, rA[i].w);
            *(uint2*)(aP + (arow + i * 16) * (ROW_H * 2) + ac4 * 8) = h;
        }
    };
    auto CPB = [&](int ct) {
        uint32_t bB = sb + (ct % NSTG) * STAGE_B + A_STAGE_B;
        const __half* Bp = g_Rth + (size_t)(cb + ct) * 64;
#pragma unroll
        for (int i = 0; i < 2; ++i) {
            int idx = tid + i * 256;        // 0..511: 64 rows x 8 chunks
            int n = idx >> 3, c = idx & 7;
            cp16(bB + n * (ROW_H * 2) + c * 16, Bp + (size_t)n * NN + c * 8);
        }
    };

    // preamble: stages 0,1 filled; A regs staged for chunk 2
    LDGA(0); STSA(0);
    LDGA(1); STSA(1);
    CPB(0); CP_COMMIT();
    CPB(1); CP_COMMIT();
    LDGA(2);

    for (int ct = 0; ct < CHPS; ++ct) {
        CP_WAIT1();          // this thread's B(ct) group complete
        __syncthreads();     // publish ALL threads' cp.async B(ct) + STS A(ct);
                             // stage (ct-1)%3 == (ct+2)%3 now provably free

        if (ct + 2 < CHPS) {
            STSA(ct + 2);    // rA holds LDGA(ct+2) from previous iteration
            CPB(ct + 2);
            if (ct + 3 < CHPS) LDGA(ct + 3);
        }
        CP_COMMIT();         // unconditional: keeps group numbering aligned

        const __half* sA = (const __half*)(smem + (ct % NSTG) * STAGE_B);
        const __half* sB = (const __half*)(smem + (ct % NSTG) * STAGE_B + A_STAGE_B);

#pragma unroll
        for (int ks = 0; ks < 4; ++ks) {
            uint32_t a[2][4], b[4][2];
            int kb = ks * 16;
#pragma unroll
            for (int mi = 0; mi < 2; ++mi) {
                int r = wm * 32 + mi * 16 + g;
                a[mi][0] = *(const uint32_t*)&sA[r * ROW_H + kb + 2 * t];
                a[mi][1] = *(const uint32_t*)&sA[(r + 8) * ROW_H + kb + 2 * t];
                a[mi][2] = *(const uint32_t*)&sA[r * ROW_H + kb + 8 + 2 * t];
                a[mi][3] = *(const uint32_t*)&sA[(r + 8) * ROW_H + kb + 8 + 2 * t];
            }
#pragma unroll
            for (int ni = 0; ni < 4; ++ni) {
                int n = wn * 32 + ni * 8 + g;
                b[ni][0] = *(const uint32_t*)&sB[n * ROW_H + kb + 2 * t];
                b[ni][1] = *(const uint32_t*)&sB[n * ROW_H + kb + 8 + 2 * t];
            }
#pragma unroll
            for (int mi = 0; mi < 2; ++mi)
#pragma unroll
                for (int ni = 0; ni < 4; ++ni)
                    mma_f16(acc[mi][ni], a[mi], b[ni]);
        }
    }

    // epilogue: red.v2 accumulate; split 0 adds self-loop + bias
    const float aLv = *paL, aHv = *paH;
    const bool  z0  = (blockIdx.y == 0);
#pragma unroll
    for (int mi = 0; mi < 2; ++mi) {
#pragma unroll
        for (int half = 0; half < 2; ++half) {
            int row = m0 + wm * 32 + mi * 16 + half * 8 + g;
            float d2 = 1.0f / (float)g_deg[row];
            size_t rb = (size_t)row * 64;
#pragma unroll
            for (int ni = 0; ni < 4; ++ni) {
                int c = wn * 32 + ni * 8 + t * 2;
                float vx = aHv * acc[mi][ni][half * 2 + 0];
                float vy = aHv * acc[mi][ni][half * 2 + 1];
                if (z0) {
                    uint32_t hw = *(const uint32_t*)&g_XWh[rb + c];
                    float2 xw = __half22float2(*(__half2*)&hw);
                    float2 bb = *(const float2*)&bconv[c];
                    vx += aLv * (d2 * xw.x + bb.x);
                    vy += aLv * (d2 * xw.y + bb.y);
                }
                red2(&out[rb + c], vx, vy);
            }
        }
    }
}

// ---------------------------------------------------------------------------
extern "C" void kernel_launch(void* const* d_in, const int* in_sizes, int n_in,
                              void* d_out, int out_size) {
    const float* x  = (const float*)d_in[0];
    const int*   ei = (const int*)d_in[1];
    const float* Ls = (const float*)d_in[2];
    const float* Wh = (const float*)d_in[3];
    const float* Wc = (const float*)d_in[4];
    const float* bc = (const float*)d_in[5];
    const float* aL = (const float*)d_in[6];
    const float* aH = (const float*)d_in[7];
    float* out = (float*)d_out;

    cudaFuncSetAttribute(k_xw,   cudaFuncAttributeMaxDynamicSharedMemorySize, SM_XW);
    cudaFuncSetAttribute(k_gemm, cudaFuncAttributeMaxDynamicSharedMemorySize, SM_GEMM);

    // order kept so ncu (-s 5 -c 1) captures k_gemm (4th launch)
    k_init<<<(NN * DD) / 256, 256>>>(out);
    k_deg<<<(EE + 255) / 256, 256>>>(ei);
    k_xw<<<96, 256, SM_XW>>>(x, Wh, Wc);
    k_gemm<<<dim3(96, KSPLIT), 256, SM_GEMM>>>(Ls, bc, aL, aH, out);
    k_scatter<<<(EE * 16) / 256, 256>>>(ei, aL, out);
}

// round 13
// speedup vs baseline: 1.3603x; 1.0441x over previous
#include <cuda_runtime.h>
#include <cuda_fp16.h>
#include <cstdint>

#define NN 12288
#define EE 196608
#define DD 64
#define KSPLIT 3
#define CHPS 64                   // chunks of BK=64 per split (192 total / 3)
#define NSTG 3
#define ROW_H 72                  // fp16 row pitch: 64 halves + 8 pad = 144 B
#define A_STAGE_B (128 * ROW_H * 2)     // 18432
#define B_STAGE_B (64 * ROW_H * 2)      // 9216
#define STAGE_B (A_STAGE_B + B_STAGE_B) // 27648
#define SM_GEMM (NSTG * STAGE_B)        // 82944 (x2 CTAs = 166KB/SM)
#define XW_ROW_F 68
#define XT_P 72                          // transpose tile pitch (64 rows + 8 pad)
#define SM_XW ((64 + 128) * XW_ROW_F * 4)  // 52224

// scratch (device globals — no allocation allowed)
__device__ __half g_Rth[DD * NN]; // relu(x @ Wh^T)^T as fp16, [feat][node]
__device__ __half g_XWh[NN * DD]; // x @ Wc^T as fp16, [node][64]
__device__ int    g_deg[NN];

// ---------------------------------------------------------------------------
__device__ __forceinline__ uint32_t smem_u32(const void* p) {
    uint32_t a;
    asm("{ .reg .u64 t; cvta.to.shared.u64 t, %1; cvt.u32.u64 %0, t; }"
        : "=r"(a) : "l"(p));
    return a;
}

__device__ __forceinline__ uint32_t f2tf32(float x) {
    uint32_t t;
    asm("cvt.rna.tf32.f32 %0, %1;" : "=r"(t) : "f"(x));
    return t;
}

__device__ __forceinline__ uint32_t pkh2(float lo, float hi) {
    __half2 h = __floats2half2_rn(lo, hi);
    return *(uint32_t*)&h;
}

__device__ __forceinline__ void cp16(uint32_t dst, const void* src) {
    asm volatile("cp.async.cg.shared.global [%0], [%1], 16;"
                 :: "r"(dst), "l"(__cvta_generic_to_global(src)) : "memory");
}
#define CP_COMMIT() asm volatile("cp.async.commit_group;" ::: "memory")
#define CP_WAIT1()  asm volatile("cp.async.wait_group 1;"  ::: "memory")
#define CP_WAIT0()  asm volatile("cp.async.wait_group 0;"  ::: "memory")

__device__ __forceinline__ void mma_tf32(float* c, const uint32_t* a, const uint32_t* b) {
    asm volatile(
        "mma.sync.aligned.m16n8k8.row.col.f32.tf32.tf32.f32 "
        "{%0,%1,%2,%3}, {%4,%5,%6,%7}, {%8,%9}, {%0,%1,%2,%3};"
        : "+f"(c[0]), "+f"(c[1]), "+f"(c[2]), "+f"(c[3])
        : "r"(a[0]), "r"(a[1]), "r"(a[2]), "r"(a[3]), "r"(b[0]), "r"(b[1]));
}

__device__ __forceinline__ void mma_f16(float* c, const uint32_t* a, const uint32_t* b) {
    asm volatile(
        "mma.sync.aligned.m16n8k16.row.col.f32.f16.f16.f32 "
        "{%0,%1,%2,%3}, {%4,%5,%6,%7}, {%8,%9}, {%0,%1,%2,%3};"
        : "+f"(c[0]), "+f"(c[1]), "+f"(c[2]), "+f"(c[3])
        : "r"(a[0]), "r"(a[1]), "r"(a[2]), "r"(a[3]), "r"(b[0]), "r"(b[1]));
}

__device__ __forceinline__ void red2(float* p, float x, float y) {
    asm volatile("red.global.add.v2.f32 [%0], {%1,%2};"
                 :: "l"(__cvta_generic_to_global(p)), "f"(x), "f"(y) : "memory");
}
__device__ __forceinline__ void red4(float* p, float x, float y, float z, float w) {
    asm volatile("red.global.add.v4.f32 [%0], {%1,%2,%3,%4};"
                 :: "l"(__cvta_generic_to_global(p)), "f"(x), "f"(y), "f"(z), "f"(w)
                 : "memory");
}

// ---------------------------------------------------------------------------
__global__ void k_init(float* __restrict__ out) {
    int i = blockIdx.x * 256 + threadIdx.x;   // grid = NN*DD/256
    out[i] = 0.0f;
    if (i < NN) g_deg[i] = 1;
}

__global__ void k_deg(const int* __restrict__ ei) {
    int e = blockIdx.x * 256 + threadIdx.x;
    if (e < EE) atomicAdd(&g_deg[ei[EE + e]], 1);
}

// ---------------------------------------------------------------------------
// Fused projections via tensor cores: [R | XW] = x @ [Wh ; Wc]^T
// 192 CTAs x 64 rows. R written as fp16 TRANSPOSED [64][NN] (SMEM bounce),
// XW as fp16 [NN][64]. 8 warps: wm=w>>1 (16-row strip), wn=w&1 (64-col half).
// ---------------------------------------------------------------------------
__global__ void __launch_bounds__(256) k_xw(const float* __restrict__ x,
                                            const float* __restrict__ Wh,
                                            const float* __restrict__ Wc) {
    extern __shared__ char smem[];
    const uint32_t sb = smem_u32(smem);
    const float* sX = (const float*)smem;
    const float* sW = (const float*)(smem + 64 * XW_ROW_F * 4);
    const uint32_t sWb = sb + 64 * XW_ROW_F * 4;

    const int tid  = threadIdx.x;
    const int lane = tid & 31;
    const int w    = tid >> 5;
    const int wm   = w >> 1;          // 0..3: 16-row strip
    const int wn   = w & 1;           // 0: R cols, 1: XW cols
    const int g    = lane >> 2;
    const int t    = lane & 3;
    const int m0   = blockIdx.x * 64;

    // load x tile [64][64]
#pragma unroll
    for (int i = 0; i < 4; ++i) {
        int idx = tid + i * 256;
        int r = idx >> 4, c = idx & 15;
        cp16(sb + r * (XW_ROW_F * 4) + c * 16, x + (size_t)(m0 + r) * 64 + c * 4);
    }
    // load stacked W [128][64]
#pragma unroll
    for (int i = 0; i < 8; ++i) {
        int idx = tid + i * 256;
        int r = idx >> 4, c = idx & 15;
        const float* wsrc = (r < 64) ? (Wh + (size_t)r * 64 + c * 4)
                                     : (Wc + (size_t)(r - 64) * 64 + c * 4);
        cp16(sWb + r * (XW_ROW_F * 4) + c * 16, wsrc);
    }
    CP_COMMIT();
    CP_WAIT0();
    __syncthreads();

    float acc[8][4];
#pragma unroll
    for (int ni = 0; ni < 8; ++ni)
#pragma unroll
        for (int q = 0; q < 4; ++q) acc[ni][q] = 0.f;

#pragma unroll
    for (int ks = 0; ks < 8; ++ks) {
        int kc = ks * 8 + t;
        uint32_t a[4], b[8][2];
        int r = wm * 16 + g;
        a[0] = f2tf32(sX[r * XW_ROW_F + kc]);
        a[1] = f2tf32(sX[(r + 8) * XW_ROW_F + kc]);
        a[2] = f2tf32(sX[r * XW_ROW_F + kc + 4]);
        a[3] = f2tf32(sX[(r + 8) * XW_ROW_F + kc + 4]);
#pragma unroll
        for (int ni = 0; ni < 8; ++ni) {
            int n = wn * 64 + ni * 8 + g;
            b[ni][0] = f2tf32(sW[n * XW_ROW_F + kc]);
            b[ni][1] = f2tf32(sW[n * XW_ROW_F + kc + 4]);
        }
#pragma unroll
        for (int ni = 0; ni < 8; ++ni)
            mma_tf32(acc[ni], a, b[ni]);
    }

    __syncthreads();   // reuse smem (x region) as fp16 transpose tile
    __half* sT = (__half*)smem;   // [64 cols][XT_P=72] fp16

#pragma unroll
    for (int half = 0; half < 2; ++half) {
        int rloc = wm * 16 + half * 8 + g;      // 0..63
        size_t rb = (size_t)(m0 + rloc) * 64;
#pragma unroll
        for (int ni = 0; ni < 8; ++ni) {
            int c = ni * 8 + t * 2;             // 0..63
            float v0 = acc[ni][half * 2 + 0];
            float v1 = acc[ni][half * 2 + 1];
            if (wn == 0) {   // R branch: relu + fp16, transpose in SMEM
                sT[(c + 0) * XT_P + rloc] = __float2half_rn(fmaxf(v0, 0.f));
                sT[(c + 1) * XT_P + rloc] = __float2half_rn(fmaxf(v1, 0.f));
            } else {         // XW branch: fp16 row-major
                *(uint32_t*)&g_XWh[rb + c] = pkh2(v0, v1);
            }
        }
    }
    __syncthreads();

    // coalesced store of transposed fp16 R tile: 64 feat-rows x 128B
#pragma unroll
    for (int i = 0; i < 2; ++i) {
        int idx = tid + i * 256;        // 0..511 16B slots
        int c = idx >> 3, j = idx & 7;
        uint4 v = *(const uint4*)&sT[c * XT_P + j * 8];
        *(uint4*)&g_Rth[(size_t)c * NN + m0 + j * 8] = v;
    }
}

// ---------------------------------------------------------------------------
// edge scatter straight into out: out[col] += aL * dinv[r]*dinv[c] * XW[row]
// ---------------------------------------------------------------------------
__global__ void __launch_bounds__(256) k_scatter(const int* __restrict__ ei,
                                                 const float* __restrict__ paL,
                                                 float* __restrict__ out) {
    int tt = blockIdx.x * 256 + threadIdx.x;   // grid = EE*16/256
    int e = tt >> 4;
    int q = tt & 15;
    int r = ei[e];
    int c = ei[EE + e];
    float norm = (*paL) * rsqrtf((float)g_deg[r]) * rsqrtf((float)g_deg[c]);
    uint2 hv = *(const uint2*)&g_XWh[(size_t)r * 64 + q * 4];
    float2 f0 = __half22float2(*(__half2*)&hv.x);
    float2 f1 = __half22float2(*(__half2*)&hv.y);
    red4(&out[c * 64 + q * 4], norm * f0.x, norm * f0.y, norm * f1.x, norm * f1.y);
}

// ---------------------------------------------------------------------------
// Main GEMM (R12-proven, untouched): fp16 m16n8k16 mma.sync, split-K=3,
// BK=64, 3-stage pipeline, 2 CTAs/SM, 288 CTAs.
// out += aH*(Lsym@R)_partial  (+ split 0: aL*(selfloop + bias))
// ---------------------------------------------------------------------------
__global__ void __launch_bounds__(256, 2) k_gemm(const float* __restrict__ L,
                                                 const float* __restrict__ bconv,
                                                 const float* __restrict__ paL,
                                                 const float* __restrict__ paH,
                                                 float* __restrict__ out) {
    extern __shared__ char smem[];
    const int tid  = threadIdx.x;
    const int lane = tid & 31;
    const int w    = tid >> 5;
    const int wm   = w >> 1;
    const int wn   = w & 1;
    const int g    = lane >> 2;
    const int t    = lane & 3;
    const int m0   = blockIdx.x * 128;
    const int cb   = blockIdx.y * CHPS;
    const uint32_t sb = smem_u32(smem);

    float acc[2][4][4];
#pragma unroll
    for (int mi = 0; mi < 2; ++mi)
#pragma unroll
        for (int ni = 0; ni < 4; ++ni)
#pragma unroll
            for (int q = 0; q < 4; ++q) acc[mi][ni][q] = 0.f;

    const int arow = tid >> 4;       // base row (8 rows x16 apart)
    const int ac4  = tid & 15;       // float4 col within 64

    float4 rA[8];                    // staged A chunk (fp32 from DRAM)

    auto LDGA = [&](int ct) {
        const float* Ap = L + (size_t)m0 * NN + (size_t)(cb + ct) * 64;
#pragma unroll
        for (int i = 0; i < 8; ++i)
            rA[i] = *(const float4*)(Ap + (size_t)(arow + i * 16) * NN + ac4 * 4);
    };
    auto STSA = [&](int ct) {
        char* aP = smem + (ct % NSTG) * STAGE_B;
#pragma unroll
        for (int i = 0; i < 8; ++i) {
            uint2 h;
            h.x = pkh2(rA[i].x, rA[i].y);
            h.y = pkh2(rA[i].z, rA[i].w);
            *(uint2*)(aP + (arow + i * 16) * (ROW_H * 2) + ac4 * 8) = h;
        }
    };
    auto CPB = [&](int ct) {
        uint32_t bB = sb + (ct % NSTG) * STAGE_B + A_STAGE_B;
        const __half* Bp = g_Rth + (size_t)(cb + ct) * 64;
#pragma unroll
        for (int i = 0; i < 2; ++i) {
            int idx = tid + i * 256;        // 0..511: 64 rows x 8 chunks
            int n = idx >> 3, c = idx & 7;
            cp16(bB + n * (ROW_H * 2) + c * 16, Bp + (size_t)n * NN + c * 8);
        }
    };

    // preamble: stages 0,1 filled; A regs staged for chunk 2
    LDGA(0); STSA(0);
    LDGA(1); STSA(1);
    CPB(0); CP_COMMIT();
    CPB(1); CP_COMMIT();
    LDGA(2);

    for (int ct = 0; ct < CHPS; ++ct) {
        CP_WAIT1();          // this thread's B(ct) group complete
        __syncthreads();     // publish ALL threads' cp.async B(ct) + STS A(ct);
                             // stage (ct-1)%3 == (ct+2)%3 now provably free

        if (ct + 2 < CHPS) {
            STSA(ct + 2);    // rA holds LDGA(ct+2) from previous iteration
            CPB(ct + 2);
            if (ct + 3 < CHPS) LDGA(ct + 3);
        }
        CP_COMMIT();         // unconditional: keeps group numbering aligned

        const __half* sA = (const __half*)(smem + (ct % NSTG) * STAGE_B);
        const __half* sB = (const __half*)(smem + (ct % NSTG) * STAGE_B + A_STAGE_B);

#pragma unroll
        for (int ks = 0; ks < 4; ++ks) {
            uint32_t a[2][4], b[4][2];
            int kb = ks * 16;
#pragma unroll
            for (int mi = 0; mi < 2; ++mi) {
                int r = wm * 32 + mi * 16 + g;
                a[mi][0] = *(const uint32_t*)&sA[r * ROW_H + kb + 2 * t];
                a[mi][1] = *(const uint32_t*)&sA[(r + 8) * ROW_H + kb + 2 * t];
                a[mi][2] = *(const uint32_t*)&sA[r * ROW_H + kb + 8 + 2 * t];
                a[mi][3] = *(const uint32_t*)&sA[(r + 8) * ROW_H + kb + 8 + 2 * t];
            }
#pragma unroll
            for (int ni = 0; ni < 4; ++ni) {
                int n = wn * 32 + ni * 8 + g;
                b[ni][0] = *(const uint32_t*)&sB[n * ROW_H + kb + 2 * t];
                b[ni][1] = *(const uint32_t*)&sB[n * ROW_H + kb + 8 + 2 * t];
            }
#pragma unroll
            for (int mi = 0; mi < 2; ++mi)
#pragma unroll
                for (int ni = 0; ni < 4; ++ni)
                    mma_f16(acc[mi][ni], a[mi], b[ni]);
        }
    }

    // epilogue: red.v2 accumulate; split 0 adds self-loop + bias
    const float aLv = *paL, aHv = *paH;
    const bool  z0  = (blockIdx.y == 0);
#pragma unroll
    for (int mi = 0; mi < 2; ++mi) {
#pragma unroll
        for (int half = 0; half < 2; ++half) {
            int row = m0 + wm * 32 + mi * 16 + half * 8 + g;
            float d2 = 1.0f / (float)g_deg[row];
            size_t rb = (size_t)row * 64;
#pragma unroll
            for (int ni = 0; ni < 4; ++ni) {
                int c = wn * 32 + ni * 8 + t * 2;
                float vx = aHv * acc[mi][ni][half * 2 + 0];
                float vy = aHv * acc[mi][ni][half * 2 + 1];
                if (z0) {
                    uint32_t hw = *(const uint32_t*)&g_XWh[rb + c];
                    float2 xw = __half22float2(*(__half2*)&hw);
                    float2 bb = *(const float2*)&bconv[c];
                    vx += aLv * (d2 * xw.x + bb.x);
                    vy += aLv * (d2 * xw.y + bb.y);
                }
                red2(&out[rb + c], vx, vy);
            }
        }
    }
}

// ---------------------------------------------------------------------------
// Stream-forked launch DAG (capture-safe fork/join):
//   s0: init -> deg ----\                    /-> (join)
//   s1: xw -------------+--> gemm (s0, after xw+deg)
//                        \-> scatter (s1, after xw+deg) -> join to s0
// gemm and scatter run CONCURRENTLY (both only red.add into out).
// Streams/events created once on the first (pre-capture) call.
// ---------------------------------------------------------------------------
extern "C" void kernel_launch(void* const* d_in, const int* in_sizes, int n_in,
                              void* d_out, int out_size) {
    const float* x  = (const float*)d_in[0];
    const int*   ei = (const int*)d_in[1];
    const float* Ls = (const float*)d_in[2];
    const float* Wh = (const float*)d_in[3];
    const float* Wc = (const float*)d_in[4];
    const float* bc = (const float*)d_in[5];
    const float* aL = (const float*)d_in[6];
    const float* aH = (const float*)d_in[7];
    float* out = (float*)d_out;

    static cudaStream_t s1 = nullptr;
    static cudaEvent_t eFork, eXW, eDeg, eSc;
    if (!s1) {
        cudaStreamCreateWithFlags(&s1, cudaStreamNonBlocking);
        cudaEventCreateWithFlags(&eFork, cudaEventDisableTiming);
        cudaEventCreateWithFlags(&eXW,   cudaEventDisableTiming);
        cudaEventCreateWithFlags(&eDeg,  cudaEventDisableTiming);
        cudaEventCreateWithFlags(&eSc,   cudaEventDisableTiming);
        cudaFuncSetAttribute(k_xw,   cudaFuncAttributeMaxDynamicSharedMemorySize, SM_XW);
        cudaFuncSetAttribute(k_gemm, cudaFuncAttributeMaxDynamicSharedMemorySize, SM_GEMM);
    }

    // fork s1 off the main stream
    cudaEventRecord(eFork, 0);
    cudaStreamWaitEvent(s1, eFork, 0);

    // s1: projections (independent of init/deg)
    k_xw<<<NN / 64, 256, SM_XW, s1>>>(x, Wh, Wc);
    cudaEventRecord(eXW, s1);

    // s0: zero out + degree
    k_init<<<(NN * DD) / 256, 256>>>(out);
    k_deg<<<(EE + 255) / 256, 256>>>(ei);
    cudaEventRecord(eDeg, 0);

    // s1: scatter after {xw (program order), init+deg (event)}
    cudaStreamWaitEvent(s1, eDeg, 0);
    k_scatter<<<(EE * 16) / 256, 256, 0, s1>>>(ei, aL, out);
    cudaEventRecord(eSc, s1);

    // s0: gemm after {init+deg (program order), xw (event)}; runs alongside scatter
    cudaStreamWaitEvent(0, eXW, 0);
    k_gemm<<<dim3(96, KSPLIT), 256, SM_GEMM>>>(Ls, bc, aL, aH, out);

    // join s1 back into s0
    cudaStreamWaitEvent(0, eSc, 0);
}

// round 14
// speedup vs baseline: 1.4952x; 1.0992x over previous
#include <cuda_runtime.h>
#include <cuda_fp16.h>
#include <cstdint>

#define NN 12288
#define EE 196608
#define DD 64
#define KSPLIT 3
#define CHPS 64                   // chunks of BK=64 per split (192 total / 3)
#define NSTG 3
#define ROW_H 72                  // fp16 row pitch: 64 halves + 8 pad = 144 B
#define A_STAGE_B (128 * ROW_H * 2)     // 18432
#define B_STAGE_B (64 * ROW_H * 2)      // 9216
#define STAGE_B (A_STAGE_B + B_STAGE_B) // 27648
#define SM_GEMM (NSTG * STAGE_B)        // 82944 (x2 CTAs = 166KB/SM)
#define XW_ROW_F 68
#define XT_P 72                          // transpose tile pitch (64 rows + 8 pad)
#define SM_XW ((64 + 128) * XW_ROW_F * 4)  // 52224

// scratch (device globals — no allocation allowed)
__device__ __half g_Rth[DD * NN]; // relu(x @ Wh^T)^T as fp16, [feat][node]
__device__ __half g_XWh[NN * DD]; // x @ Wc^T as fp16, [node][64]
__device__ int    g_deg[NN];

// ---------------------------------------------------------------------------
__device__ __forceinline__ uint32_t smem_u32(const void* p) {
    uint32_t a;
    asm("{ .reg .u64 t; cvta.to.shared.u64 t, %1; cvt.u32.u64 %0, t; }"
        : "=r"(a) : "l"(p));
    return a;
}

__device__ __forceinline__ uint32_t f2tf32(float x) {
    uint32_t t;
    asm("cvt.rna.tf32.f32 %0, %1;" : "=r"(t) : "f"(x));
    return t;
}

__device__ __forceinline__ uint32_t pkh2(float lo, float hi) {
    __half2 h = __floats2half2_rn(lo, hi);
    return *(uint32_t*)&h;
}

__device__ __forceinline__ void cp16(uint32_t dst, const void* src) {
    asm volatile("cp.async.cg.shared.global [%0], [%1], 16;"
                 :: "r"(dst), "l"(__cvta_generic_to_global(src)) : "memory");
}
#define CP_COMMIT() asm volatile("cp.async.commit_group;" ::: "memory")
#define CP_WAIT1()  asm volatile("cp.async.wait_group 1;"  ::: "memory")
#define CP_WAIT0()  asm volatile("cp.async.wait_group 0;"  ::: "memory")

__device__ __forceinline__ void mma_tf32(float* c, const uint32_t* a, const uint32_t* b) {
    asm volatile(
        "mma.sync.aligned.m16n8k8.row.col.f32.tf32.tf32.f32 "
        "{%0,%1,%2,%3}, {%4,%5,%6,%7}, {%8,%9}, {%0,%1,%2,%3};"
        : "+f"(c[0]), "+f"(c[1]), "+f"(c[2]), "+f"(c[3])
        : "r"(a[0]), "r"(a[1]), "r"(a[2]), "r"(a[3]), "r"(b[0]), "r"(b[1]));
}

__device__ __forceinline__ void mma_f16(float* c, const uint32_t* a, const uint32_t* b) {
    asm volatile(
        "mma.sync.aligned.m16n8k16.row.col.f32.f16.f16.f32 "
        "{%0,%1,%2,%3}, {%4,%5,%6,%7}, {%8,%9}, {%0,%1,%2,%3};"
        : "+f"(c[0]), "+f"(c[1]), "+f"(c[2]), "+f"(c[3])
        : "r"(a[0]), "r"(a[1]), "r"(a[2]), "r"(a[3]), "r"(b[0]), "r"(b[1]));
}

__device__ __forceinline__ void red2(float* p, float x, float y) {
    asm volatile("red.global.add.v2.f32 [%0], {%1,%2};"
                 :: "l"(__cvta_generic_to_global(p)), "f"(x), "f"(y) : "memory");
}
__device__ __forceinline__ void red4(float* p, float x, float y, float z, float w) {
    asm volatile("red.global.add.v4.f32 [%0], {%1,%2,%3,%4};"
                 :: "l"(__cvta_generic_to_global(p)), "f"(x), "f"(y), "f"(z), "f"(w)
                 : "memory");
}

// ---------------------------------------------------------------------------
__global__ void k_init(float* __restrict__ out) {
    int i = blockIdx.x * 256 + threadIdx.x;   // grid = NN*DD/256
    out[i] = 0.0f;
    if (i < NN) g_deg[i] = 1;
}

__global__ void k_deg(const int* __restrict__ ei) {
    int e = blockIdx.x * 256 + threadIdx.x;
    if (e < EE) atomicAdd(&g_deg[ei[EE + e]], 1);
}

// ---------------------------------------------------------------------------
// Fused projections via tensor cores: [R | XW] = x @ [Wh ; Wc]^T
// 192 CTAs x 64 rows. R written as fp16 TRANSPOSED [64][NN] (SMEM bounce),
// XW as fp16 [NN][64].
// ---------------------------------------------------------------------------
__global__ void __launch_bounds__(256) k_xw(const float* __restrict__ x,
                                            const float* __restrict__ Wh,
                                            const float* __restrict__ Wc) {
    extern __shared__ char smem[];
    const uint32_t sb = smem_u32(smem);
    const float* sX = (const float*)smem;
    const float* sW = (const float*)(smem + 64 * XW_ROW_F * 4);
    const uint32_t sWb = sb + 64 * XW_ROW_F * 4;

    const int tid  = threadIdx.x;
    const int lane = tid & 31;
    const int w    = tid >> 5;
    const int wm   = w >> 1;          // 0..3: 16-row strip
    const int wn   = w & 1;           // 0: R cols, 1: XW cols
    const int g    = lane >> 2;
    const int t    = lane & 3;
    const int m0   = blockIdx.x * 64;

#pragma unroll
    for (int i = 0; i < 4; ++i) {
        int idx = tid + i * 256;
        int r = idx >> 4, c = idx & 15;
        cp16(sb + r * (XW_ROW_F * 4) + c * 16, x + (size_t)(m0 + r) * 64 + c * 4);
    }
#pragma unroll
    for (int i = 0; i < 8; ++i) {
        int idx = tid + i * 256;
        int r = idx >> 4, c = idx & 15;
        const float* wsrc = (r < 64) ? (Wh + (size_t)r * 64 + c * 4)
                                     : (Wc + (size_t)(r - 64) * 64 + c * 4);
        cp16(sWb + r * (XW_ROW_F * 4) + c * 16, wsrc);
    }
    CP_COMMIT();
    CP_WAIT0();
    __syncthreads();

    float acc[8][4];
#pragma unroll
    for (int ni = 0; ni < 8; ++ni)
#pragma unroll
        for (int q = 0; q < 4; ++q) acc[ni][q] = 0.f;

#pragma unroll
    for (int ks = 0; ks < 8; ++ks) {
        int kc = ks * 8 + t;
        uint32_t a[4], b[8][2];
        int r = wm * 16 + g;
        a[0] = f2tf32(sX[r * XW_ROW_F + kc]);
        a[1] = f2tf32(sX[(r + 8) * XW_ROW_F + kc]);
        a[2] = f2tf32(sX[r * XW_ROW_F + kc + 4]);
        a[3] = f2tf32(sX[(r + 8) * XW_ROW_F + kc + 4]);
#pragma unroll
        for (int ni = 0; ni < 8; ++ni) {
            int n = wn * 64 + ni * 8 + g;
            b[ni][0] = f2tf32(sW[n * XW_ROW_F + kc]);
            b[ni][1] = f2tf32(sW[n * XW_ROW_F + kc + 4]);
        }
#pragma unroll
        for (int ni = 0; ni < 8; ++ni)
            mma_tf32(acc[ni], a, b[ni]);
    }

    __syncthreads();   // reuse smem (x region) as fp16 transpose tile
    __half* sT = (__half*)smem;   // [64 cols][XT_P=72] fp16

#pragma unroll
    for (int half = 0; half < 2; ++half) {
        int rloc = wm * 16 + half * 8 + g;      // 0..63
        size_t rb = (size_t)(m0 + rloc) * 64;
#pragma unroll
        for (int ni = 0; ni < 8; ++ni) {
            int c = ni * 8 + t * 2;             // 0..63
            float v0 = acc[ni][half * 2 + 0];
            float v1 = acc[ni][half * 2 + 1];
            if (wn == 0) {
                sT[(c + 0) * XT_P + rloc] = __float2half_rn(fmaxf(v0, 0.f));
                sT[(c + 1) * XT_P + rloc] = __float2half_rn(fmaxf(v1, 0.f));
            } else {
                *(uint32_t*)&g_XWh[rb + c] = pkh2(v0, v1);
            }
        }
    }
    __syncthreads();

#pragma unroll
    for (int i = 0; i < 2; ++i) {
        int idx = tid + i * 256;        // 0..511 16B slots
        int c = idx >> 3, j = idx & 7;
        uint4 v = *(const uint4*)&sT[c * XT_P + j * 8];
        *(uint4*)&g_Rth[(size_t)c * NN + m0 + j * 8] = v;
    }
}

// ---------------------------------------------------------------------------
// edge scatter straight into out: out[col] += aL * dinv[r]*dinv[c] * XW[row]
// ---------------------------------------------------------------------------
__global__ void __launch_bounds__(256) k_scatter(const int* __restrict__ ei,
                                                 const float* __restrict__ paL,
                                                 float* __restrict__ out) {
    int tt = blockIdx.x * 256 + threadIdx.x;   // grid = EE*16/256
    int e = tt >> 4;
    int q = tt & 15;
    int r = ei[e];
    int c = ei[EE + e];
    float norm = (*paL) * rsqrtf((float)g_deg[r]) * rsqrtf((float)g_deg[c]);
    uint2 hv = *(const uint2*)&g_XWh[(size_t)r * 64 + q * 4];
    float2 f0 = __half22float2(*(__half2*)&hv.x);
    float2 f1 = __half22float2(*(__half2*)&hv.y);
    red4(&out[c * 64 + q * 4], norm * f0.x, norm * f0.y, norm * f1.x, norm * f1.y);
}

// ---------------------------------------------------------------------------
// Main GEMM (R12 config + __ldcs streaming A): fp16 m16n8k16 mma.sync,
// split-K=3, BK=64, 3-stage pipeline, 2 CTAs/SM, 288 CTAs.
// Lsym is read-once (604MB): evict-first keeps L2 for B/out/scatter set.
// out += aH*(Lsym@R)_partial  (+ split 0: aL*(selfloop + bias))
// ---------------------------------------------------------------------------
__global__ void __launch_bounds__(256, 2) k_gemm(const float* __restrict__ L,
                                                 const float* __restrict__ bconv,
                                                 const float* __restrict__ paL,
                                                 const float* __restrict__ paH,
                                                 float* __restrict__ out) {
    extern __shared__ char smem[];
    const int tid  = threadIdx.x;
    const int lane = tid & 31;
    const int w    = tid >> 5;
    const int wm   = w >> 1;
    const int wn   = w & 1;
    const int g    = lane >> 2;
    const int t    = lane & 3;
    const int m0   = blockIdx.x * 128;
    const int cb   = blockIdx.y * CHPS;
    const uint32_t sb = smem_u32(smem);

    float acc[2][4][4];
#pragma unroll
    for (int mi = 0; mi < 2; ++mi)
#pragma unroll
        for (int ni = 0; ni < 4; ++ni)
#pragma unroll
            for (int q = 0; q < 4; ++q) acc[mi][ni][q] = 0.f;

    const int arow = tid >> 4;       // base row (8 rows x16 apart)
    const int ac4  = tid & 15;       // float4 col within 64

    float4 rA[8];                    // staged A chunk (fp32 from DRAM)

    auto LDGA = [&](int ct) {
        const float* Ap = L + (size_t)m0 * NN + (size_t)(cb + ct) * 64;
#pragma unroll
        for (int i = 0; i < 8; ++i)
            rA[i] = __ldcs((const float4*)(Ap + (size_t)(arow + i * 16) * NN + ac4 * 4));
    };
    auto STSA = [&](int ct) {
        char* aP = smem + (ct % NSTG) * STAGE_B;
#pragma unroll
        for (int i = 0; i < 8; ++i) {
            uint2 h;
            h.x = pkh2(rA[i].x, rA[i].y);
            h.y = pkh2(rA[i].z, rA[i].w);
            *(uint2*)(aP + (arow + i * 16) * (ROW_H * 2) + ac4 * 8) = h;
        }
    };
    auto CPB = [&](int ct) {
        uint32_t bB = sb + (ct % NSTG) * STAGE_B + A_STAGE_B;
        const __half* Bp = g_Rth + (size_t)(cb + ct) * 64;
#pragma unroll
        for (int i = 0; i < 2; ++i) {
            int idx = tid + i * 256;        // 0..511: 64 rows x 8 chunks
            int n = idx >> 3, c = idx & 7;
            cp16(bB + n * (ROW_H * 2) + c * 16, Bp + (size_t)n * NN + c * 8);
        }
    };

    // preamble: stages 0,1 filled; A regs staged for chunk 2
    LDGA(0); STSA(0);
    LDGA(1); STSA(1);
    CPB(0); CP_COMMIT();
    CPB(1); CP_COMMIT();
    LDGA(2);

    for (int ct = 0; ct < CHPS; ++ct) {
        CP_WAIT1();          // this thread's B(ct) group complete
        __syncthreads();     // publish ALL threads' cp.async B(ct) + STS A(ct);
                             // stage (ct-1)%3 == (ct+2)%3 now provably free

        if (ct + 2 < CHPS) {
            STSA(ct + 2);    // rA holds LDGA(ct+2) from previous iteration
            CPB(ct + 2);
            if (ct + 3 < CHPS) LDGA(ct + 3);
        }
        CP_COMMIT();         // unconditional: keeps group numbering aligned

        const __half* sA = (const __half*)(smem + (ct % NSTG) * STAGE_B);
        const __half* sB = (const __half*)(smem + (ct % NSTG) * STAGE_B + A_STAGE_B);

#pragma unroll
        for (int ks = 0; ks < 4; ++ks) {
            uint32_t a[2][4], b[4][2];
            int kb = ks * 16;
#pragma unroll
            for (int mi = 0; mi < 2; ++mi) {
                int r = wm * 32 + mi * 16 + g;
                a[mi][0] = *(const uint32_t*)&sA[r * ROW_H + kb + 2 * t];
                a[mi][1] = *(const uint32_t*)&sA[(r + 8) * ROW_H + kb + 2 * t];
                a[mi][2] = *(const uint32_t*)&sA[r * ROW_H + kb + 8 + 2 * t];
                a[mi][3] = *(const uint32_t*)&sA[(r + 8) * ROW_H + kb + 8 + 2 * t];
            }
#pragma unroll
            for (int ni = 0; ni < 4; ++ni) {
                int n = wn * 32 + ni * 8 + g;
                b[ni][0] = *(const uint32_t*)&sB[n * ROW_H + kb + 2 * t];
                b[ni][1] = *(const uint32_t*)&sB[n * ROW_H + kb + 8 + 2 * t];
            }
#pragma unroll
            for (int mi = 0; mi < 2; ++mi)
#pragma unroll
                for (int ni = 0; ni < 4; ++ni)
                    mma_f16(acc[mi][ni], a[mi], b[ni]);
        }
    }

    // epilogue: red.v2 accumulate; split 0 adds self-loop + bias
    const float aLv = *paL, aHv = *paH;
    const bool  z0  = (blockIdx.y == 0);
#pragma unroll
    for (int mi = 0; mi < 2; ++mi) {
#pragma unroll
        for (int half = 0; half < 2; ++half) {
            int row = m0 + wm * 32 + mi * 16 + half * 8 + g;
            float d2 = 1.0f / (float)g_deg[row];
            size_t rb = (size_t)row * 64;
#pragma unroll
            for (int ni = 0; ni < 4; ++ni) {
                int c = wn * 32 + ni * 8 + t * 2;
                float vx = aHv * acc[mi][ni][half * 2 + 0];
                float vy = aHv * acc[mi][ni][half * 2 + 1];
                if (z0) {
                    uint32_t hw = *(const uint32_t*)&g_XWh[rb + c];
                    float2 xw = __half22float2(*(__half2*)&hw);
                    float2 bb = *(const float2*)&bconv[c];
                    vx += aLv * (d2 * xw.x + bb.x);
                    vy += aLv * (d2 * xw.y + bb.y);
                }
                red2(&out[rb + c], vx, vy);
            }
        }
    }
}

// ---------------------------------------------------------------------------
// Stream-forked launch DAG (unchanged from R13):
//   s0: init -> deg ; s1: xw  ->  gemm (s0) || scatter (s1)  -> join
// ---------------------------------------------------------------------------
extern "C" void kernel_launch(void* const* d_in, const int* in_sizes, int n_in,
                              void* d_out, int out_size) {
    const float* x  = (const float*)d_in[0];
    const int*   ei = (const int*)d_in[1];
    const float* Ls = (const float*)d_in[2];
    const float* Wh = (const float*)d_in[3];
    const float* Wc = (const float*)d_in[4];
    const float* bc = (const float*)d_in[5];
    const float* aL = (const float*)d_in[6];
    const float* aH = (const float*)d_in[7];
    float* out = (float*)d_out;

    static cudaStream_t s1 = nullptr;
    static cudaEvent_t eFork, eXW, eDeg, eSc;
    if (!s1) {
        cudaStreamCreateWithFlags(&s1, cudaStreamNonBlocking);
        cudaEventCreateWithFlags(&eFork, cudaEventDisableTiming);
        cudaEventCreateWithFlags(&eXW,   cudaEventDisableTiming);
        cudaEventCreateWithFlags(&eDeg,  cudaEventDisableTiming);
        cudaEventCreateWithFlags(&eSc,   cudaEventDisableTiming);
        cudaFuncSetAttribute(k_xw,   cudaFuncAttributeMaxDynamicSharedMemorySize, SM_XW);
        cudaFuncSetAttribute(k_gemm, cudaFuncAttributeMaxDynamicSharedMemorySize, SM_GEMM);
    }

    // fork s1 off the main stream
    cudaEventRecord(eFork, 0);
    cudaStreamWaitEvent(s1, eFork, 0);

    // s1: projections (independent of init/deg)
    k_xw<<<NN / 64, 256, SM_XW, s1>>>(x, Wh, Wc);
    cudaEventRecord(eXW, s1);

    // s0: zero out + degree
    k_init<<<(NN * DD) / 256, 256>>>(out);
    k_deg<<<(EE + 255) / 256, 256>>>(ei);
    cudaEventRecord(eDeg, 0);

    // s1: scatter after {xw (program order), init+deg (event)}
    cudaStreamWaitEvent(s1, eDeg, 0);
    k_scatter<<<(EE * 16) / 256, 256, 0, s1>>>(ei, aL, out);
    cudaEventRecord(eSc, s1);

    // s0: gemm after {init+deg (program order), xw (event)}; runs alongside scatter
    cudaStreamWaitEvent(0, eXW, 0);
    k_gemm<<<dim3(96, KSPLIT), 256, SM_GEMM>>>(Ls, bc, aL, aH, out);

    // join s1 back into s0
    cudaStreamWaitEvent(0, eSc, 0);
}